// round 1
// baseline (speedup 1.0000x reference)
#include <cuda_runtime.h>
#include <cstdint>
#include <cstddef>

// ---------------- constants ----------------
#define BATCH   16
#define GRID_   16
#define NTOK    256
#define TOK     4096          // BATCH*NTOK
#define HID     1152
#define HEADS   16
#define DH      72
#define QKVN    3456
#define MLPN    4608
#define ADAN    6912
#define WIN     4

// ---------------- scratch (device globals; no allocation allowed) ----------------
__device__ float g_h  [TOK * HID];
__device__ float g_x1 [TOK * HID];
__device__ float g_qkv[TOK * QKVN];
__device__ float g_ao [TOK * HID];
__device__ float g_mh [TOK * MLPN];
__device__ float g_e1 [BATCH * HID];
__device__ float g_c  [BATCH * HID];
__device__ float g_scb[BATCH * HID];     // silu(c)
__device__ float g_mod [BATCH * ADAN];
__device__ float g_fmod[BATCH * 2304];

// ---------------- math helpers ----------------
__device__ __forceinline__ float silu_f(float x) { return x / (1.f + expf(-x)); }
__device__ __forceinline__ float gelu_f(float x) {
    float x3 = x * x * x;
    return 0.5f * x * (1.f + tanhf(0.7978845608028654f * (x + 0.044715f * x3)));
}

// Keys cubic kernel (a=-0.5), jax.image.resize semantics: half-pixel sampling,
// per-output normalization over in-range taps. 4 -> 16 upsample.
__device__ __forceinline__ void bicubic_w(int i, float w[4]) {
    float s = (i + 0.5f) * 0.25f - 0.5f;
    float tot = 0.f;
#pragma unroll
    for (int j = 0; j < 4; j++) {
        float x = fabsf(s - (float)j);
        float v;
        if (x >= 2.f)      v = 0.f;
        else if (x >= 1.f) v = ((-0.5f * x + 2.5f) * x - 4.f) * x + 2.f;
        else               v = ((1.5f * x - 2.5f) * x) * x + 1.f;
        w[j] = v; tot += v;
    }
    float inv = 1.f / tot;
#pragma unroll
    for (int j = 0; j < 4; j++) w[j] *= inv;
}

// ---------------- patchify + pos-embed ----------------
__global__ void __launch_bounds__(288) patchify_kernel(
    const float* __restrict__ x, const float* __restrict__ pw,
    const float* __restrict__ pb, const float* __restrict__ pe)
{
    int t = blockIdx.x;
    int b = t >> 8, gy = (t >> 4) & 15, gx = t & 15;

    float xr[16];
#pragma unroll
    for (int ic = 0; ic < 4; ic++)
#pragma unroll
        for (int py = 0; py < 2; py++)
#pragma unroll
            for (int px = 0; px < 2; px++)
                xr[ic * 4 + py * 2 + px] =
                    x[(((size_t)b * 4 + ic) * 32 + (gy * 2 + py)) * 32 + gx * 2 + px];

    float wy[4], wx[4];
    bicubic_w(gy, wy); bicubic_w(gx, wx);
    float wyx[16];
#pragma unroll
    for (int jy = 0; jy < 4; jy++)
#pragma unroll
        for (int jx = 0; jx < 4; jx++) wyx[jy * 4 + jx] = wy[jy] * wx[jx];

    for (int o = threadIdx.x; o < HID; o += 288) {
        float a = pb[o];
        const float* w = pw + (size_t)o * 16;
#pragma unroll
        for (int q = 0; q < 16; q++) a += xr[q] * w[q];
        float p = 0.f;
#pragma unroll
        for (int q = 0; q < 16; q++) p += wyx[q] * pe[(size_t)q * HID + o];
        g_h[(size_t)t * HID + o] = a + p;
    }
}

// ---------------- timestep embedding ----------------
__global__ void __launch_bounds__(256) temb1_kernel(
    const float* __restrict__ tin, const float* __restrict__ w1, const float* __restrict__ b1)
{
    int b = blockIdx.x;
    __shared__ float te[256];
    int tid = threadIdx.x;
    float tv = tin[b];
    {
        float fr = expf(-9.210340371976184f * (float)(tid & 127) / 128.f);
        float arg = tv * fr;
        te[tid] = (tid < 128) ? cosf(arg) : sinf(arg);
    }
    __syncthreads();
    for (int j = tid; j < HID; j += 256) {
        float acc = b1[j];
        for (int k = 0; k < 256; k++) acc += te[k] * w1[(size_t)k * HID + j];
        g_e1[b * HID + j] = silu_f(acc);
    }
}

__global__ void __launch_bounds__(256) temb2_kernel(
    const float* __restrict__ w2, const float* __restrict__ b2,
    const float* __restrict__ ytab, const int* __restrict__ y)
{
    int b = blockIdx.x;
    __shared__ float e[HID];
    int tid = threadIdx.x;
    for (int k = tid; k < HID; k += 256) e[k] = g_e1[b * HID + k];
    __syncthreads();
    int yb = y[b];
    for (int j = tid; j < HID; j += 256) {
        float acc = b2[j] + ytab[(size_t)yb * HID + j];
        for (int k = 0; k < HID; k++) acc += e[k] * w2[(size_t)k * HID + j];
        g_c[b * HID + j] = acc;
        g_scb[b * HID + j] = silu_f(acc);
    }
}

// ---------------- small conditioning GEMM: out[b][j] = silu_c[b] . W[:,j] + bias ----------------
__global__ void __launch_bounds__(256) modk_kernel(
    const float* __restrict__ W, const float* __restrict__ bias,
    float* __restrict__ out, int Nout)
{
    int b = blockIdx.y;
    int j = blockIdx.x * 256 + threadIdx.x;
    __shared__ float s[HID];
    for (int k = threadIdx.x; k < HID; k += 256) s[k] = g_scb[b * HID + k];
    __syncthreads();
    float acc = bias[j];
    for (int k = 0; k < HID; k++) acc += s[k] * W[(size_t)k * Nout + j];
    out[(size_t)b * Nout + j] = acc;
}

// ---------------- LayerNorm + adaLN modulate: g_x1 = ln(g_h)*(1+sc)+sh ----------------
__global__ void __launch_bounds__(288) ln_mod_kernel(
    const float* __restrict__ sh, const float* __restrict__ sc, int mstride)
{
    int t = blockIdx.x;
    int b = t >> 8;
    int tid = threadIdx.x;
    const float* row = g_h + (size_t)t * HID;
    float v[4]; float s = 0.f, s2 = 0.f;
#pragma unroll
    for (int k = 0; k < 4; k++) {
        float xv = row[tid + k * 288];
        v[k] = xv; s += xv; s2 += xv * xv;
    }
#pragma unroll
    for (int o = 16; o > 0; o >>= 1) {
        s  += __shfl_xor_sync(0xffffffffu, s, o);
        s2 += __shfl_xor_sync(0xffffffffu, s2, o);
    }
    __shared__ float ws[9], ws2[9];
    int w = tid >> 5, lane = tid & 31;
    if (lane == 0) { ws[w] = s; ws2[w] = s2; }
    __syncthreads();
    if (tid == 0) {
        float a = 0.f, a2 = 0.f;
        for (int i = 0; i < 9; i++) { a += ws[i]; a2 += ws2[i]; }
        ws[0] = a; ws2[0] = a2;
    }
    __syncthreads();
    float mean = ws[0] * (1.f / HID);
    float var  = ws2[0] * (1.f / HID) - mean * mean;
    float rstd = rsqrtf(var + 1e-6f);
    const float* shr = sh + (size_t)b * mstride;
    const float* scr = sc + (size_t)b * mstride;
    float* orow = g_x1 + (size_t)t * HID;
#pragma unroll
    for (int k = 0; k < 4; k++) {
        int j = tid + k * 288;
        float xm = (v[k] - mean) * rstd;
        orow[j] = xm * (1.f + scr[j]) + shr[j];
    }
}

// ---------------- generic fp32 GEMM, 64x64x16 tiles, templated epilogue ----------------
// EPI 0: C = acc + bias
// EPI 1: C = gelu(acc + bias)
// EPI 2: C += gate[b][n] * (acc + bias)     (gate stride = gstride)
template<int EPI>
__global__ void __launch_bounds__(256) gemm_kernel(
    const float* __restrict__ A, const float* __restrict__ B,
    const float* __restrict__ bias, float* __restrict__ C,
    const float* __restrict__ gate, int gstride, int N, int K)
{
    __shared__ float As[16][68];
    __shared__ float Bs[16][68];
    int tid = threadIdx.x;
    int m0 = blockIdx.y * 64;
    int n0 = blockIdx.x * 64;
    int tx = tid & 15, ty = tid >> 4;

    int arow = tid >> 2;
    int acol = (tid & 3) * 4;
    int brow = tid >> 4;
    int bcol = (tid & 15) * 4;

    const float* Aptr = A + (size_t)(m0 + arow) * K + acol;
    const float* Bptr = B + (size_t)brow * N + n0 + bcol;

    float acc[4][4] = {};

    for (int k0 = 0; k0 < K; k0 += 16) {
        float4 av = *(const float4*)Aptr;
        Aptr += 16;
        As[acol + 0][arow] = av.x;
        As[acol + 1][arow] = av.y;
        As[acol + 2][arow] = av.z;
        As[acol + 3][arow] = av.w;
        float4 bv = *(const float4*)Bptr;
        Bptr += (size_t)16 * N;
        *(float4*)&Bs[brow][bcol] = bv;
        __syncthreads();
#pragma unroll
        for (int kk = 0; kk < 16; kk++) {
            float4 a = *(const float4*)&As[kk][ty * 4];
            float4 bq = *(const float4*)&Bs[kk][tx * 4];
            float ar[4] = {a.x, a.y, a.z, a.w};
            float br[4] = {bq.x, bq.y, bq.z, bq.w};
#pragma unroll
            for (int i = 0; i < 4; i++)
#pragma unroll
                for (int j = 0; j < 4; j++)
                    acc[i][j] = fmaf(ar[i], br[j], acc[i][j]);
        }
        __syncthreads();
    }

    int bidx = m0 >> 8;   // all 64 rows of this tile share one batch index
#pragma unroll
    for (int i = 0; i < 4; i++) {
        int m = m0 + ty * 4 + i;
#pragma unroll
        for (int j = 0; j < 4; j++) {
            int n = n0 + tx * 4 + j;
            float v = acc[i][j] + bias[n];
            size_t off = (size_t)m * N + n;
            if (EPI == 1) v = gelu_f(v);
            if (EPI == 2) C[off] += gate[(size_t)bidx * gstride + n] * v;
            else          C[off] = v;
        }
    }
}

// ---------------- neighborhood attention (4x4 window, 16 heads, dh=72) ----------------
__global__ void __launch_bounds__(256) attn_kernel()
{
    int t = blockIdx.x;
    int b = t >> 8, i = (t >> 4) & 15, j = t & 15;
    int tid = threadIdx.x;
    int h = tid >> 4, p = tid & 15;

    __shared__ int   ntok[16];
    __shared__ float att[16][16];

    if (tid < 16) {
        int py = tid >> 2, px = tid & 3;
        int si = min(max(i - 2, 0), 12);
        int sj = min(max(j - 2, 0), 12);
        ntok[tid] = (b << 8) | ((si + py) << 4) | (sj + px);
    }
    __syncthreads();

    const float* qrow = g_qkv + (size_t)t * QKVN + h * DH;
    const float* krow = g_qkv + (size_t)ntok[p] * QKVN + HID + h * DH;
    float acc = 0.f;
#pragma unroll 8
    for (int d = 0; d < DH; d++) acc += qrow[d] * krow[d];
    acc *= 0.11785113019775793f;   // 72^-0.5

    float m = acc;
#pragma unroll
    for (int o = 8; o > 0; o >>= 1) m = fmaxf(m, __shfl_xor_sync(0xffffffffu, m, o, 16));
    float e = expf(acc - m);
    float s = e;
#pragma unroll
    for (int o = 8; o > 0; o >>= 1) s += __shfl_xor_sync(0xffffffffu, s, o, 16);
    att[h][p] = e / s;
    __syncthreads();

    for (int o = tid; o < HID; o += 256) {
        int hh = o / DH;
        float sum = 0.f;
#pragma unroll
        for (int p2 = 0; p2 < 16; p2++)
            sum += att[hh][p2] * g_qkv[(size_t)ntok[p2] * QKVN + 2304 + o];
        g_ao[(size_t)t * HID + o] = sum;
    }
}

// ---------------- final linear (1152 -> 32) + unpatchify scatter ----------------
__global__ void __launch_bounds__(256) final_kernel(
    const float* __restrict__ flw, const float* __restrict__ flb, float* __restrict__ out)
{
    int t = blockIdx.x;
    int b = t >> 8, gy = (t >> 4) & 15, gx = t & 15;
    __shared__ float xs[HID];
    __shared__ float part[8][32];
    int tid = threadIdx.x;
    for (int k = tid; k < HID; k += 256) xs[k] = g_x1[(size_t)t * HID + k];
    __syncthreads();
    int col = tid & 31, seg = tid >> 5;   // 8 segments x 144
    float acc = 0.f;
    int k0 = seg * 144;
    for (int k = k0; k < k0 + 144; k++)
        acc += xs[k] * flw[(size_t)k * 32 + col];
    part[seg][col] = acc;
    __syncthreads();
    if (tid < 32) {
        float s = flb[tid];
#pragma unroll
        for (int sg = 0; sg < 8; sg++) s += part[sg][tid];
        int ch = tid & 7, pq = tid >> 3, p = pq >> 1, q = pq & 1;
        out[(((size_t)b * 8 + ch) * 32 + gy * 2 + p) * 32 + gx * 2 + q] = s;
    }
}

// ---------------- launch ----------------
extern "C" void kernel_launch(void* const* d_in, const int* in_sizes, int n_in,
                              void* d_out, int out_size)
{
    const float* x    = (const float*)d_in[0];
    const float* tin  = (const float*)d_in[1];
    const int*   y    = (const int*)  d_in[2];
    const float* pos  = (const float*)d_in[3];
    const float* pw   = (const float*)d_in[4];
    const float* pb   = (const float*)d_in[5];
    const float* tw1  = (const float*)d_in[6];
    const float* tb1  = (const float*)d_in[7];
    const float* tw2  = (const float*)d_in[8];
    const float* tb2  = (const float*)d_in[9];
    const float* ytab = (const float*)d_in[10];
    const float* adaw = (const float*)d_in[11];
    const float* adab = (const float*)d_in[12];
    const float* qkvw = (const float*)d_in[13];
    const float* qkvb = (const float*)d_in[14];
    const float* prjw = (const float*)d_in[15];
    const float* prjb = (const float*)d_in[16];
    const float* m1w  = (const float*)d_in[17];
    const float* m1b  = (const float*)d_in[18];
    const float* m2w  = (const float*)d_in[19];
    const float* m2b  = (const float*)d_in[20];
    const float* flaw = (const float*)d_in[21];
    const float* flab = (const float*)d_in[22];
    const float* flw  = (const float*)d_in[23];
    const float* flb  = (const float*)d_in[24];
    float* out = (float*)d_out;

    float *p_x1, *p_qkv, *p_ao, *p_mh, *p_h, *p_mod, *p_fmod;
    cudaGetSymbolAddress((void**)&p_x1,  g_x1);
    cudaGetSymbolAddress((void**)&p_qkv, g_qkv);
    cudaGetSymbolAddress((void**)&p_ao,  g_ao);
    cudaGetSymbolAddress((void**)&p_mh,  g_mh);
    cudaGetSymbolAddress((void**)&p_h,   g_h);
    cudaGetSymbolAddress((void**)&p_mod, g_mod);
    cudaGetSymbolAddress((void**)&p_fmod, g_fmod);

    patchify_kernel<<<TOK, 288>>>(x, pw, pb, pos);
    temb1_kernel<<<BATCH, 256>>>(tin, tw1, tb1);
    temb2_kernel<<<BATCH, 256>>>(tw2, tb2, ytab, y);

    for (int l = 0; l < 2; l++) {
        const float* aw = adaw + (size_t)l * HID * ADAN;
        const float* ab = adab + (size_t)l * ADAN;
        modk_kernel<<<dim3(ADAN / 256, BATCH), 256>>>(aw, ab, p_mod, ADAN);

        // attention block
        ln_mod_kernel<<<TOK, 288>>>(p_mod + 0, p_mod + HID, ADAN);
        gemm_kernel<0><<<dim3(QKVN / 64, TOK / 64), 256>>>(
            p_x1, qkvw + (size_t)l * HID * QKVN, qkvb + (size_t)l * QKVN,
            p_qkv, nullptr, 0, QKVN, HID);
        attn_kernel<<<TOK, 256>>>();
        gemm_kernel<2><<<dim3(HID / 64, TOK / 64), 256>>>(
            p_ao, prjw + (size_t)l * HID * HID, prjb + (size_t)l * HID,
            p_h, p_mod + 2 * HID, ADAN, HID, HID);

        // mlp block
        ln_mod_kernel<<<TOK, 288>>>(p_mod + 3 * HID, p_mod + 4 * HID, ADAN);
        gemm_kernel<1><<<dim3(MLPN / 64, TOK / 64), 256>>>(
            p_x1, m1w + (size_t)l * HID * MLPN, m1b + (size_t)l * MLPN,
            p_mh, nullptr, 0, MLPN, HID);
        gemm_kernel<2><<<dim3(HID / 64, TOK / 64), 256>>>(
            p_mh, m2w + (size_t)l * MLPN * HID, m2b + (size_t)l * HID,
            p_h, p_mod + 5 * HID, ADAN, HID, MLPN);
    }

    // final layer
    modk_kernel<<<dim3(2304 / 256, BATCH), 256>>>(flaw, flab, p_fmod, 2304);
    ln_mod_kernel<<<TOK, 288>>>(p_fmod + 0, p_fmod + HID, 2304);
    final_kernel<<<TOK, 256>>>(flw, flb, out);

    (void)in_sizes; (void)n_in; (void)out_size;
}

// round 3
// speedup vs baseline: 2.5774x; 2.5774x over previous
#include <cuda_runtime.h>
#include <cstdint>
#include <cstddef>

// ---------------- constants ----------------
#define BATCH   16
#define TOK     4096
#define HID     1152
#define QKVN    3456
#define MLPN    4608
#define ADAN    6912
#define DH      72

// ---------------- scratch ----------------
__device__ float g_h  [TOK * HID];
__device__ float g_x1 [TOK * HID];
__device__ float g_qkv[TOK * QKVN];
__device__ float g_ao [TOK * HID];
__device__ float g_mh [TOK * MLPN];
__device__ float g_e1 [BATCH * HID];
__device__ float g_c  [BATCH * HID];
__device__ float g_scb[BATCH * HID];
__device__ float g_mod [BATCH * ADAN];
__device__ float g_fmod[BATCH * 2304];
__device__ float g_wt  [MLPN * HID];      // transposed+tf32 weight staging (max 4608x1152)

// ---------------- helpers ----------------
__device__ __forceinline__ float silu_f(float x) { return x / (1.f + expf(-x)); }
__device__ __forceinline__ float gelu_f(float x) {
    float x3 = x * x * x;
    return 0.5f * x * (1.f + tanhf(0.7978845608028654f * (x + 0.044715f * x3)));
}
__device__ __forceinline__ float tf32r(float x) {
    float r;
    asm("cvt.rna.tf32.f32 %0, %1;" : "=f"(r) : "f"(x));
    return r;
}
__device__ __forceinline__ uint32_t su32(const void* p) {
    uint32_t a;
    asm("{ .reg .u64 t; cvta.to.shared.u64 t, %1; cvt.u32.u64 %0, t; }" : "=r"(a) : "l"(p));
    return a;
}
__device__ __forceinline__ void cpa16(uint32_t dst, const float* src) {
    asm volatile("cp.async.cg.shared.global [%0], [%1], 16;" :: "r"(dst), "l"(src) : "memory");
}
__device__ __forceinline__ void cpa_commit() {
    asm volatile("cp.async.commit_group;" ::: "memory");
}
__device__ __forceinline__ void mma8(float* d, const float* a, const float* b) {
    asm volatile("mma.sync.aligned.m16n8k8.row.col.f32.tf32.tf32.f32 "
                 "{%0,%1,%2,%3}, {%4,%5,%6,%7}, {%8,%9}, {%0,%1,%2,%3};"
                 : "+f"(d[0]), "+f"(d[1]), "+f"(d[2]), "+f"(d[3])
                 : "r"(__float_as_uint(a[0])), "r"(__float_as_uint(a[1])),
                   "r"(__float_as_uint(a[2])), "r"(__float_as_uint(a[3])),
                   "r"(__float_as_uint(b[0])), "r"(__float_as_uint(b[1])));
}

// ---------------- weight transpose + tf32 convert: WT[n][k] = tf32(W[k][n]) ----------------
__global__ void __launch_bounds__(256) wtrans_kernel(
    const float* __restrict__ W, float* __restrict__ WT, int K, int N)
{
    __shared__ float tile[32][33];
    int n0 = blockIdx.x * 32, k0 = blockIdx.y * 32;
    int tx = threadIdx.x & 31, ty = threadIdx.x >> 5;   // 32 x 8
#pragma unroll
    for (int i = 0; i < 32; i += 8)
        tile[ty + i][tx] = W[(size_t)(k0 + ty + i) * N + n0 + tx];
    __syncthreads();
#pragma unroll
    for (int i = 0; i < 32; i += 8)
        WT[(size_t)(n0 + ty + i) * K + k0 + tx] = tf32r(tile[tx][ty + i]);
}

// ---------------- tf32 mma.sync GEMM: C[4096 x N] = A[4096 x K] * WT[N x K]^T ----------------
// EPI 0: C = acc + bias ; EPI 1: C = tf32(gelu(acc+bias)) ; EPI 2: C += gate[b][n]*(acc+bias)
#define GSME 73728

template<int EPI>
__global__ void __launch_bounds__(256, 2) mma_gemm(
    const float* __restrict__ A, const float* __restrict__ WT,
    const float* __restrict__ bias, float* __restrict__ C,
    const float* __restrict__ gate, int gstride, int N, int K)
{
    extern __shared__ float sm[];           // As: 2*128*36, Bs: 2*128*36
    float* As = sm;
    float* Bs = sm + 9216;
    uint32_t smB = su32(sm);

    int tid = threadIdx.x;
    int m0 = blockIdx.y * 128, n0 = blockIdx.x * 128;
    int lane = tid & 31, wid = tid >> 5;
    int wm = wid >> 2, wn = wid & 3;        // warp tile: rows wm*64, cols wn*32
    int g = lane >> 2, q = lane & 3;

    const float* Abase = A  + (size_t)m0 * K;
    const float* Bbase = WT + (size_t)n0 * K;

    const int NC = K >> 5;
    float acc[4][4][4];
#pragma unroll
    for (int i = 0; i < 4; i++)
#pragma unroll
        for (int j = 0; j < 4; j++)
#pragma unroll
            for (int r = 0; r < 4; r++) acc[i][j][r] = 0.f;

    // prefetch chunk 0 into buf 0
    {
#pragma unroll
        for (int i = 0; i < 4; i++) {
            int idx = tid + i * 256;
            int r = idx >> 3, c4 = (idx & 7) * 4;
            cpa16(smB + (size_t)( (r * 36 + c4) * 4 ),            Abase + (size_t)r * K + c4);
            cpa16(smB + (size_t)( (9216 + r * 36 + c4) * 4 ),     Bbase + (size_t)r * K + c4);
        }
        cpa_commit();
    }

    for (int c = 0; c < NC; c++) {
        int buf = c & 1;
        if (c + 1 < NC) {
            int nb = buf ^ 1;
            const float* Ab = Abase + (c + 1) * 32;
            const float* Bb = Bbase + (c + 1) * 32;
#pragma unroll
            for (int i = 0; i < 4; i++) {
                int idx = tid + i * 256;
                int r = idx >> 3, c4 = (idx & 7) * 4;
                cpa16(smB + (size_t)((nb * 4608 + r * 36 + c4) * 4),        Ab + (size_t)r * K + c4);
                cpa16(smB + (size_t)((9216 + nb * 4608 + r * 36 + c4) * 4), Bb + (size_t)r * K + c4);
            }
            cpa_commit();
            asm volatile("cp.async.wait_group 1;" ::: "memory");
        } else {
            asm volatile("cp.async.wait_group 0;" ::: "memory");
        }
        __syncthreads();

        const float* Abuf = As + buf * 4608 + (wm * 64 + g) * 36;
        const float* Bbuf = Bs + buf * 4608 + (wn * 32 + g) * 36;
#pragma unroll
        for (int ks = 0; ks < 4; ks++) {
            int ko = ks * 8 + q;
            float a[4][4], b[4][2];
#pragma unroll
            for (int mi = 0; mi < 4; mi++) {
                const float* p = Abuf + mi * 16 * 36 + ko;
                a[mi][0] = p[0];
                a[mi][1] = p[8 * 36];
                a[mi][2] = p[4];
                a[mi][3] = p[8 * 36 + 4];
            }
#pragma unroll
            for (int ni = 0; ni < 4; ni++) {
                const float* p = Bbuf + ni * 8 * 36 + ko;
                b[ni][0] = p[0];
                b[ni][1] = p[4];
            }
#pragma unroll
            for (int mi = 0; mi < 4; mi++)
#pragma unroll
                for (int ni = 0; ni < 4; ni++)
                    mma8(acc[mi][ni], a[mi], b[ni]);
        }
        __syncthreads();
    }

    // ---- epilogue ----
    int bidx = m0 >> 8;
#pragma unroll
    for (int mi = 0; mi < 4; mi++) {
#pragma unroll
        for (int half = 0; half < 2; half++) {
            int row = m0 + wm * 64 + mi * 16 + g + half * 8;
            float* Crow = C + (size_t)row * N;
#pragma unroll
            for (int ni = 0; ni < 4; ni++) {
                int col = n0 + wn * 32 + ni * 8 + 2 * q;
                float2 bv = *(const float2*)(bias + col);
                float v0 = acc[mi][ni][half * 2 + 0] + bv.x;
                float v1 = acc[mi][ni][half * 2 + 1] + bv.y;
                if (EPI == 1) { v0 = tf32r(gelu_f(v0)); v1 = tf32r(gelu_f(v1)); }
                if (EPI == 2) {
                    float2 gv = *(const float2*)(gate + (size_t)bidx * gstride + col);
                    float2 cv = *(float2*)(Crow + col);
                    cv.x += gv.x * v0; cv.y += gv.y * v1;
                    *(float2*)(Crow + col) = cv;
                } else {
                    float2 ov = make_float2(v0, v1);
                    *(float2*)(Crow + col) = ov;
                }
            }
        }
    }
}

// ---------------- bicubic ----------------
__device__ __forceinline__ void bicubic_w(int i, float w[4]) {
    float s = (i + 0.5f) * 0.25f - 0.5f;
    float tot = 0.f;
#pragma unroll
    for (int j = 0; j < 4; j++) {
        float x = fabsf(s - (float)j);
        float v;
        if (x >= 2.f)      v = 0.f;
        else if (x >= 1.f) v = ((-0.5f * x + 2.5f) * x - 4.f) * x + 2.f;
        else               v = ((1.5f * x - 2.5f) * x) * x + 1.f;
        w[j] = v; tot += v;
    }
    float inv = 1.f / tot;
#pragma unroll
    for (int j = 0; j < 4; j++) w[j] *= inv;
}

// ---------------- patchify + pos-embed ----------------
__global__ void __launch_bounds__(288) patchify_kernel(
    const float* __restrict__ x, const float* __restrict__ pw,
    const float* __restrict__ pb, const float* __restrict__ pe)
{
    int t = blockIdx.x;
    int b = t >> 8, gy = (t >> 4) & 15, gx = t & 15;

    float xr[16];
#pragma unroll
    for (int ic = 0; ic < 4; ic++)
#pragma unroll
        for (int py = 0; py < 2; py++)
#pragma unroll
            for (int px = 0; px < 2; px++)
                xr[ic * 4 + py * 2 + px] =
                    x[(((size_t)b * 4 + ic) * 32 + (gy * 2 + py)) * 32 + gx * 2 + px];

    float wy[4], wx[4];
    bicubic_w(gy, wy); bicubic_w(gx, wx);
    float wyx[16];
#pragma unroll
    for (int jy = 0; jy < 4; jy++)
#pragma unroll
        for (int jx = 0; jx < 4; jx++) wyx[jy * 4 + jx] = wy[jy] * wx[jx];

    for (int o = threadIdx.x; o < HID; o += 288) {
        float a = pb[o];
        const float* w = pw + (size_t)o * 16;
#pragma unroll
        for (int qq = 0; qq < 16; qq++) a += xr[qq] * w[qq];
        float p = 0.f;
#pragma unroll
        for (int qq = 0; qq < 16; qq++) p += wyx[qq] * pe[(size_t)qq * HID + o];
        g_h[(size_t)t * HID + o] = a + p;
    }
}

// ---------------- timestep embedding ----------------
__global__ void __launch_bounds__(256) temb1_kernel(
    const float* __restrict__ tin, const float* __restrict__ w1, const float* __restrict__ b1)
{
    int b = blockIdx.x;
    __shared__ float te[256];
    int tid = threadIdx.x;
    float tv = tin[b];
    {
        float fr = expf(-9.210340371976184f * (float)(tid & 127) / 128.f);
        float arg = tv * fr;
        te[tid] = (tid < 128) ? cosf(arg) : sinf(arg);
    }
    __syncthreads();
    for (int j = tid; j < HID; j += 256) {
        float acc = b1[j];
        for (int k = 0; k < 256; k++) acc += te[k] * w1[(size_t)k * HID + j];
        g_e1[b * HID + j] = silu_f(acc);
    }
}

__global__ void __launch_bounds__(256) temb2_kernel(
    const float* __restrict__ w2, const float* __restrict__ b2,
    const float* __restrict__ ytab, const int* __restrict__ y)
{
    int b = blockIdx.x;
    __shared__ float e[HID];
    int tid = threadIdx.x;
    for (int k = tid; k < HID; k += 256) e[k] = g_e1[b * HID + k];
    __syncthreads();
    int yb = y[b];
    for (int j = tid; j < HID; j += 256) {
        float acc = b2[j] + ytab[(size_t)yb * HID + j];
        for (int k = 0; k < HID; k++) acc += e[k] * w2[(size_t)k * HID + j];
        g_c[b * HID + j] = acc;
        g_scb[b * HID + j] = silu_f(acc);
    }
}

// ---------------- conditioning GEMV ----------------
__global__ void __launch_bounds__(288) modk_kernel(
    const float* __restrict__ W, const float* __restrict__ bias,
    float* __restrict__ out, int Nout)
{
    int b = blockIdx.y;
    int j = blockIdx.x * 1152 + threadIdx.x * 4;
    __shared__ float s[HID];
    for (int k = threadIdx.x; k < HID; k += 288) s[k] = g_scb[b * HID + k];
    __syncthreads();
    float4 acc = *(const float4*)(bias + j);
#pragma unroll 8
    for (int k = 0; k < HID; k++) {
        float sv = s[k];
        float4 wv = *(const float4*)(W + (size_t)k * Nout + j);
        acc.x += sv * wv.x; acc.y += sv * wv.y; acc.z += sv * wv.z; acc.w += sv * wv.w;
    }
    *(float4*)(out + (size_t)b * Nout + j) = acc;
}

// ---------------- LN + adaLN modulate (tf32-rounded output) ----------------
__global__ void __launch_bounds__(288) ln_mod_kernel(
    const float* __restrict__ sh, const float* __restrict__ sc, int mstride)
{
    int t = blockIdx.x;
    int b = t >> 8;
    int tid = threadIdx.x;
    const float* row = g_h + (size_t)t * HID;
    float v[4]; float s = 0.f, s2 = 0.f;
#pragma unroll
    for (int k = 0; k < 4; k++) {
        float xv = row[tid + k * 288];
        v[k] = xv; s += xv; s2 += xv * xv;
    }
#pragma unroll
    for (int o = 16; o > 0; o >>= 1) {
        s  += __shfl_xor_sync(0xffffffffu, s, o);
        s2 += __shfl_xor_sync(0xffffffffu, s2, o);
    }
    __shared__ float ws[9], ws2[9];
    int w = tid >> 5, lane = tid & 31;
    if (lane == 0) { ws[w] = s; ws2[w] = s2; }
    __syncthreads();
    if (tid == 0) {
        float a = 0.f, a2 = 0.f;
        for (int i = 0; i < 9; i++) { a += ws[i]; a2 += ws2[i]; }
        ws[0] = a; ws2[0] = a2;
    }
    __syncthreads();
    float mean = ws[0] * (1.f / HID);
    float var  = ws2[0] * (1.f / HID) - mean * mean;
    float rstd = rsqrtf(var + 1e-6f);
    const float* shr = sh + (size_t)b * mstride;
    const float* scr = sc + (size_t)b * mstride;
    float* orow = g_x1 + (size_t)t * HID;
#pragma unroll
    for (int k = 0; k < 4; k++) {
        int j = tid + k * 288;
        float xm = (v[k] - mean) * rstd;
        orow[j] = tf32r(xm * (1.f + scr[j]) + shr[j]);
    }
}

// ---------------- neighborhood attention (tf32-rounded output) ----------------
__global__ void __launch_bounds__(256) attn_kernel()
{
    int t = blockIdx.x;
    int b = t >> 8, i = (t >> 4) & 15, j = t & 15;
    int tid = threadIdx.x;
    int h = tid >> 4, p = tid & 15;

    __shared__ int   ntok[16];
    __shared__ float att[16][16];

    if (tid < 16) {
        int py = tid >> 2, px = tid & 3;
        int si = min(max(i - 2, 0), 12);
        int sj = min(max(j - 2, 0), 12);
        ntok[tid] = (b << 8) | ((si + py) << 4) | (sj + px);
    }
    __syncthreads();

    const float* qrow = g_qkv + (size_t)t * QKVN + h * DH;
    const float* krow = g_qkv + (size_t)ntok[p] * QKVN + HID + h * DH;
    float acc = 0.f;
#pragma unroll 8
    for (int d = 0; d < DH; d++) acc += qrow[d] * krow[d];
    acc *= 0.11785113019775793f;

    float m = acc;
#pragma unroll
    for (int o = 8; o > 0; o >>= 1) m = fmaxf(m, __shfl_xor_sync(0xffffffffu, m, o, 16));
    float e = expf(acc - m);
    float s = e;
#pragma unroll
    for (int o = 8; o > 0; o >>= 1) s += __shfl_xor_sync(0xffffffffu, s, o, 16);
    att[h][p] = e / s;
    __syncthreads();

    for (int o = tid; o < HID; o += 256) {
        int hh = o / DH;
        float sum = 0.f;
#pragma unroll
        for (int p2 = 0; p2 < 16; p2++)
            sum += att[hh][p2] * g_qkv[(size_t)ntok[p2] * QKVN + 2304 + o];
        g_ao[(size_t)t * HID + o] = tf32r(sum);
    }
}

// ---------------- final linear + unpatchify ----------------
__global__ void __launch_bounds__(256) final_kernel(
    const float* __restrict__ flw, const float* __restrict__ flb, float* __restrict__ out)
{
    int t = blockIdx.x;
    int b = t >> 8, gy = (t >> 4) & 15, gx = t & 15;
    __shared__ float xs[HID];
    __shared__ float part[8][32];
    int tid = threadIdx.x;
    for (int k = tid; k < HID; k += 256) xs[k] = g_x1[(size_t)t * HID + k];
    __syncthreads();
    int col = tid & 31, seg = tid >> 5;
    float acc = 0.f;
    int k0 = seg * 144;
    for (int k = k0; k < k0 + 144; k++)
        acc += xs[k] * flw[(size_t)k * 32 + col];
    part[seg][col] = acc;
    __syncthreads();
    if (tid < 32) {
        float s = flb[tid];
#pragma unroll
        for (int sg = 0; sg < 8; sg++) s += part[sg][tid];
        int ch = tid & 7, pq = tid >> 3, p = pq >> 1, q = pq & 1;
        out[(((size_t)b * 8 + ch) * 32 + gy * 2 + p) * 32 + gx * 2 + q] = s;
    }
}

// ---------------- launch ----------------
extern "C" void kernel_launch(void* const* d_in, const int* in_sizes, int n_in,
                              void* d_out, int out_size)
{
    const float* x    = (const float*)d_in[0];
    const float* tin  = (const float*)d_in[1];
    const int*   y    = (const int*)  d_in[2];
    const float* pos  = (const float*)d_in[3];
    const float* pw   = (const float*)d_in[4];
    const float* pb   = (const float*)d_in[5];
    const float* tw1  = (const float*)d_in[6];
    const float* tb1  = (const float*)d_in[7];
    const float* tw2  = (const float*)d_in[8];
    const float* tb2  = (const float*)d_in[9];
    const float* ytab = (const float*)d_in[10];
    const float* adaw = (const float*)d_in[11];
    const float* adab = (const float*)d_in[12];
    const float* qkvw = (const float*)d_in[13];
    const float* qkvb = (const float*)d_in[14];
    const float* prjw = (const float*)d_in[15];
    const float* prjb = (const float*)d_in[16];
    const float* m1w  = (const float*)d_in[17];
    const float* m1b  = (const float*)d_in[18];
    const float* m2w  = (const float*)d_in[19];
    const float* m2b  = (const float*)d_in[20];
    const float* flaw = (const float*)d_in[21];
    const float* flab = (const float*)d_in[22];
    const float* flw  = (const float*)d_in[23];
    const float* flb  = (const float*)d_in[24];
    float* out = (float*)d_out;

    float *p_x1, *p_qkv, *p_ao, *p_mh, *p_h, *p_mod, *p_fmod, *p_wt;
    cudaGetSymbolAddress((void**)&p_x1,  g_x1);
    cudaGetSymbolAddress((void**)&p_qkv, g_qkv);
    cudaGetSymbolAddress((void**)&p_ao,  g_ao);
    cudaGetSymbolAddress((void**)&p_mh,  g_mh);
    cudaGetSymbolAddress((void**)&p_h,   g_h);
    cudaGetSymbolAddress((void**)&p_mod, g_mod);
    cudaGetSymbolAddress((void**)&p_fmod, g_fmod);
    cudaGetSymbolAddress((void**)&p_wt,  g_wt);

    cudaFuncSetAttribute(mma_gemm<0>, cudaFuncAttributeMaxDynamicSharedMemorySize, GSME);
    cudaFuncSetAttribute(mma_gemm<1>, cudaFuncAttributeMaxDynamicSharedMemorySize, GSME);
    cudaFuncSetAttribute(mma_gemm<2>, cudaFuncAttributeMaxDynamicSharedMemorySize, GSME);

    patchify_kernel<<<TOK, 288>>>(x, pw, pb, pos);
    temb1_kernel<<<BATCH, 256>>>(tin, tw1, tb1);
    temb2_kernel<<<BATCH, 256>>>(tw2, tb2, ytab, y);

    for (int l = 0; l < 2; l++) {
        const float* aw = adaw + (size_t)l * HID * ADAN;
        const float* ab = adab + (size_t)l * ADAN;
        modk_kernel<<<dim3(ADAN / 1152, BATCH), 288>>>(aw, ab, p_mod, ADAN);

        // attention block
        ln_mod_kernel<<<TOK, 288>>>(p_mod + 0, p_mod + HID, ADAN);
        wtrans_kernel<<<dim3(QKVN / 32, HID / 32), 256>>>(
            qkvw + (size_t)l * HID * QKVN, p_wt, HID, QKVN);
        mma_gemm<0><<<dim3(QKVN / 128, TOK / 128), 256, GSME>>>(
            p_x1, p_wt, qkvb + (size_t)l * QKVN, p_qkv, nullptr, 0, QKVN, HID);
        attn_kernel<<<TOK, 256>>>();
        wtrans_kernel<<<dim3(HID / 32, HID / 32), 256>>>(
            prjw + (size_t)l * HID * HID, p_wt, HID, HID);
        mma_gemm<2><<<dim3(HID / 128, TOK / 128), 256, GSME>>>(
            p_ao, p_wt, prjb + (size_t)l * HID, p_h, p_mod + 2 * HID, ADAN, HID, HID);

        // mlp block
        ln_mod_kernel<<<TOK, 288>>>(p_mod + 3 * HID, p_mod + 4 * HID, ADAN);
        wtrans_kernel<<<dim3(MLPN / 32, HID / 32), 256>>>(
            m1w + (size_t)l * HID * MLPN, p_wt, HID, MLPN);
        mma_gemm<1><<<dim3(MLPN / 128, TOK / 128), 256, GSME>>>(
            p_x1, p_wt, m1b + (size_t)l * MLPN, p_mh, nullptr, 0, MLPN, HID);
        wtrans_kernel<<<dim3(HID / 32, MLPN / 32), 256>>>(
            m2w + (size_t)l * MLPN * HID, p_wt, MLPN, HID);
        mma_gemm<2><<<dim3(HID / 128, TOK / 128), 256, GSME>>>(
            p_mh, p_wt, m2b + (size_t)l * HID, p_h, p_mod + 5 * HID, ADAN, HID, MLPN);
    }

    modk_kernel<<<dim3(2304 / 1152, BATCH), 288>>>(flaw, flab, p_fmod, 2304);
    ln_mod_kernel<<<TOK, 288>>>(p_fmod + 0, p_fmod + HID, 2304);
    final_kernel<<<TOK, 256>>>(flw, flb, out);

    (void)in_sizes; (void)n_in; (void)out_size;
}